// round 8
// baseline (speedup 1.0000x reference)
#include <cuda_runtime.h>

#define DIMS 2048
#define SEQ  4096
#define SENT 2.0f            // tanh output in (-1,1), h0 = 0 -> never 2.0
#define NCTA 128
#define RPC  16
#define RNN_T 256

// ---------------- scratch (static device globals; no allocation) ------------
__device__ float g_A[SEQ * DIMS];                         // A = X @ W_hi^T + b
__device__ __align__(16) float g_hist[(SEQ + 1) * DIMS];  // write-once h history

// ---------------- asm helpers ------------------------------------------------
__device__ __forceinline__ float tanh_fast(float x) {
    float y; asm("tanh.approx.f32 %0, %1;" : "=f"(y) : "f"(x)); return y;
}
__device__ __forceinline__ float4 ldg_vol_v4(const float4* p) {
    float4 v;
    asm volatile("ld.volatile.global.v4.f32 {%0,%1,%2,%3}, [%4];"
                 : "=f"(v.x), "=f"(v.y), "=f"(v.z), "=f"(v.w) : "l"(p));
    return v;
}
__device__ __forceinline__ void stg_vol_v2(float2* p, float a, float b) {
    asm volatile("st.volatile.global.v2.f32 [%0], {%1,%2};"
                 :: "l"(p), "f"(a), "f"(b) : "memory");
}
__device__ __forceinline__ void ffma2(unsigned long long& d,
                                      unsigned long long a, unsigned long long b) {
    asm("fma.rn.f32x2 %0, %1, %2, %0;" : "+l"(d) : "l"(a), "l"(b));
}
__device__ __forceinline__ unsigned long long add2(unsigned long long a,
                                                   unsigned long long b) {
    unsigned long long s;
    asm("add.rn.f32x2 %0, %1, %2;" : "=l"(s) : "l"(a), "l"(b));
    return s;
}
__device__ __forceinline__ unsigned long long pack2(float x) {
    unsigned long long r; asm("mov.b64 %0, {%1, %1};" : "=l"(r) : "f"(x)); return r;
}
__device__ __forceinline__ float f32x2_hsum(unsigned long long a, unsigned long long b) {
    unsigned long long s = add2(a, b);
    float2 f = *reinterpret_cast<float2*>(&s);
    return f.x + f.y;
}

// ---------------- init: poison history, seed h0 -------------------------------
__global__ void poison_kernel() {
    const float4 s = make_float4(SENT, SENT, SENT, SENT);
    float4* p = (float4*)g_hist;
    const int total = (SEQ + 1) * (DIMS / 4);
    for (int w = blockIdx.x * blockDim.x + threadIdx.x; w < total;
         w += gridDim.x * blockDim.x)
        p[w] = s;
}
__global__ void seed_kernel(const float* __restrict__ h0) {
    int i = blockIdx.x * blockDim.x + threadIdx.x;
    if (i < DIMS) g_hist[i] = h0[i];
}

// ---------------- phase 1: A = X @ W^T + b  (packed f32x2 GEMM, as R5) --------
#define BM 128
#define BN 128
#define BK 8

__global__ __launch_bounds__(256) void gemm_kernel(
    const float* __restrict__ X, const float* __restrict__ W,
    const float* __restrict__ b, float* __restrict__ A)
{
    __shared__ __align__(16) float Xs[BK][BM];
    __shared__ __align__(16) float Ws[BK][BN];

    const int tid = threadIdx.x;
    const int m0  = blockIdx.y * BM;
    const int n0  = blockIdx.x * BN;
    const int tx  = tid & 15;
    const int ty  = tid >> 4;
    const int lr  = tid >> 1;
    const int lk  = (tid & 1) * 4;

    unsigned long long acc[8][4];
#pragma unroll
    for (int i = 0; i < 8; i++)
#pragma unroll
        for (int jp = 0; jp < 4; jp++) acc[i][jp] = 0ull;

    for (int k0 = 0; k0 < DIMS; k0 += BK) {
        float4 xv = *(const float4*)(X + (size_t)(m0 + lr) * DIMS + k0 + lk);
        float4 wv = *(const float4*)(W + (size_t)(n0 + lr) * DIMS + k0 + lk);
        __syncthreads();
        Xs[lk + 0][lr] = xv.x; Xs[lk + 1][lr] = xv.y;
        Xs[lk + 2][lr] = xv.z; Xs[lk + 3][lr] = xv.w;
        Ws[lk + 0][lr] = wv.x; Ws[lk + 1][lr] = wv.y;
        Ws[lk + 2][lr] = wv.z; Ws[lk + 3][lr] = wv.w;
        __syncthreads();
#pragma unroll
        for (int k = 0; k < BK; k++) {
            unsigned long long xd[8], wp[4];
#pragma unroll
            for (int i = 0; i < 8; i++) xd[i] = pack2(Xs[k][ty + 16 * i]);
#pragma unroll
            for (int jp = 0; jp < 4; jp++)
                wp[jp] = *(const unsigned long long*)&Ws[k][tx * 2 + 32 * jp];
#pragma unroll
            for (int i = 0; i < 8; i++)
#pragma unroll
                for (int jp = 0; jp < 4; jp++) ffma2(acc[i][jp], xd[i], wp[jp]);
        }
    }
    unsigned long long bp[4];
#pragma unroll
    for (int jp = 0; jp < 4; jp++)
        bp[jp] = *(const unsigned long long*)&b[n0 + tx * 2 + 32 * jp];
#pragma unroll
    for (int i = 0; i < 8; i++) {
        const int m = m0 + ty + 16 * i;
#pragma unroll
        for (int jp = 0; jp < 4; jp++) {
            *(unsigned long long*)&A[(size_t)m * DIMS + n0 + tx * 2 + 32 * jp] =
                add2(acc[i][jp], bp[jp]);
        }
    }
}

// ---------------- phase 2: persistent sequential RNN --------------------------
// R5 structure: 128 CTAs x 256 threads (8 warps, 2 rows each), hot-spin
// payload polling (NO sleep). Trims vs R5: direct lane0 v2 publish (no smem
// collect), double-buffered h_s -> single bar per step.
__global__ __launch_bounds__(RNN_T, 1) void rnn_kernel(
    const float* __restrict__ X, const float* __restrict__ Whh,
    float* __restrict__ out)
{
    __shared__ __align__(16) float4 h_s[2][DIMS / 4];   // 2 x 8 KB

    const int tid  = threadIdx.x;
    const int wid  = tid >> 5;
    const int lane = tid & 31;
    const int cta  = blockIdx.x;
    const int row0 = cta * RPC + wid * 2;
    const int row1 = row0 + 1;

    // W_hh slice in registers as packed f32x2 pairs (2 rows per warp).
    ulonglong2 w0[16], w1[16];
    {
        const ulonglong2* W0 = (const ulonglong2*)(Whh + (size_t)row0 * DIMS);
        const ulonglong2* W1 = (const ulonglong2*)(Whh + (size_t)row1 * DIMS);
#pragma unroll
        for (int k = 0; k < 16; k++) {
            w0[k] = W0[lane + 32 * k];
            w1[k] = W1[lane + 32 * k];
        }
    }

    for (int t = 0; t < SEQ; t++) {
        const int cur = t & 1;
        const float4* hb = (const float4*)(g_hist + (size_t)t * DIMS);

        // Step-constant operands, off the h critical chain.
        float a0 = 0.f, a1 = 0.f, xr0 = 0.f, xr1 = 0.f;
        if (lane == 0) {
            a0  = g_A[(size_t)t * DIMS + row0];
            a1  = g_A[(size_t)t * DIMS + row1];
            xr0 = X[(size_t)t * DIMS + row0];
            xr1 = X[(size_t)t * DIMS + row1];
        }

        // Ingest h_prev: each thread owns 2 of the 512 16B words; payload IS
        // the signal. Hot spin — no sleep, no backoff.
        {
            float4 va = ldg_vol_v4(hb + tid);
            float4 vb = ldg_vol_v4(hb + tid + RNN_T);
            while (va.x == SENT || va.y == SENT || va.z == SENT || va.w == SENT)
                va = ldg_vol_v4(hb + tid);
            while (vb.x == SENT || vb.y == SENT || vb.z == SENT || vb.w == SENT)
                vb = ldg_vol_v4(hb + tid + RNN_T);
            h_s[cur][tid]         = va;
            h_s[cur][tid + RNN_T] = vb;
        }
        __syncthreads();   // ONLY bar: h_s[cur] staged. (Reaching this bar at
                           // step t also proves all step t-2 parity reads are
                           // done, so this step's writes to h_s[cur] were safe,
                           // and step t+1 may overwrite h_s[cur^1] barless.)

        // 2 dot products per warp; W in registers, packed f32x2 FMA.
        const ulonglong2* hp = (const ulonglong2*)h_s[cur];
        unsigned long long a0x = 0ull, a0y = 0ull, a1x = 0ull, a1y = 0ull;
#pragma unroll
        for (int k = 0; k < 16; k++) {
            ulonglong2 hv = hp[lane + 32 * k];
            ffma2(a0x, w0[k].x, hv.x);  ffma2(a0y, w0[k].y, hv.y);
            ffma2(a1x, w1[k].x, hv.x);  ffma2(a1y, w1[k].y, hv.y);
        }
        float acc0 = f32x2_hsum(a0x, a0y);
        float acc1 = f32x2_hsum(a1x, a1y);
#pragma unroll
        for (int o = 16; o > 0; o >>= 1) {
            acc0 += __shfl_xor_sync(0xffffffffu, acc0, o);
            acc1 += __shfl_xor_sync(0xffffffffu, acc1, o);
        }

        if (lane == 0) {
            float h0n = tanh_fast(a0 + acc0);
            float h1n = tanh_fast(a1 + acc1);
            // Publish immediately: write-once 8B word, single publisher.
            // (row0 is even -> 8B aligned; readers poll the enclosing v4 and
            // require all 4 lanes != SENT, covering both v2 halves.)
            stg_vol_v2((float2*)(g_hist + (size_t)(t + 1) * DIMS + row0), h0n, h1n);
            out[(size_t)t * DIMS + row0] = xr0 + h0n;   // residual, off-chain
            out[(size_t)t * DIMS + row1] = xr1 + h1n;
        }
        // no second bar: publish is lane-local, h_s reuse is covered above
    }
}

// ---------------- launch -------------------------------------------------------
extern "C" void kernel_launch(void* const* d_in, const int* in_sizes, int n_in,
                              void* d_out, int out_size) {
    const float* X    = (const float*)d_in[0];  // [SEQ, DIMS]
    const float* W_hi = (const float*)d_in[1];  // [DIMS, DIMS]
    const float* W_hh = (const float*)d_in[2];  // [DIMS, DIMS]
    const float* b    = (const float*)d_in[3];  // [DIMS]
    const float* h0   = (const float*)d_in[4];  // [DIMS]
    float* out = (float*)d_out;

    float* A;
    cudaGetSymbolAddress((void**)&A, g_A);

    poison_kernel<<<1024, 256>>>();
    seed_kernel<<<(DIMS + 255) / 256, 256>>>(h0);

    dim3 ggrid(DIMS / BN, SEQ / BM);            // (16, 32)
    gemm_kernel<<<ggrid, 256>>>(X, W_hi, b, A);

    rnn_kernel<<<NCTA, RNN_T>>>(X, W_hh, out);
}

// round 9
// speedup vs baseline: 2.5395x; 2.5395x over previous
#include <cuda_runtime.h>

#define DIMS 2048
#define SEQ  4096
#define SENT 2.0f   // sentinel: tanh output is in (-1,1), h0 = 0 -> never 2.0

// ---------------- scratch (static device globals; no allocation) ------------
__device__ float g_A[SEQ * DIMS];                         // A = X @ W_hi^T + b
__device__ __align__(16) float g_hist[(SEQ + 1) * DIMS];  // write-once h history

// ---------------- small asm helpers -----------------------------------------
__device__ __forceinline__ float tanh_fast(float x) {
    float y;
    asm("tanh.approx.f32 %0, %1;" : "=f"(y) : "f"(x));
    return y;
}
__device__ __forceinline__ float4 ldg_vol_v4(const float4* p) {
    float4 v;
    asm volatile("ld.volatile.global.v4.f32 {%0,%1,%2,%3}, [%4];"
                 : "=f"(v.x), "=f"(v.y), "=f"(v.z), "=f"(v.w) : "l"(p));
    return v;
}
__device__ __forceinline__ void stg_vol_v4(float4* p, float4 v) {
    asm volatile("st.volatile.global.v4.f32 [%0], {%1,%2,%3,%4};"
                 :: "l"(p), "f"(v.x), "f"(v.y), "f"(v.z), "f"(v.w) : "memory");
}
// packed fp32x2 ops
__device__ __forceinline__ void ffma2(unsigned long long& d,
                                      unsigned long long a, unsigned long long b) {
    asm("fma.rn.f32x2 %0, %1, %2, %0;" : "+l"(d) : "l"(a), "l"(b));
}
__device__ __forceinline__ unsigned long long add2(unsigned long long a,
                                                   unsigned long long b) {
    unsigned long long s;
    asm("add.rn.f32x2 %0, %1, %2;" : "=l"(s) : "l"(a), "l"(b));
    return s;
}
__device__ __forceinline__ unsigned long long pack2(float x) {
    unsigned long long r;
    asm("mov.b64 %0, {%1, %1};" : "=l"(r) : "f"(x));
    return r;
}
__device__ __forceinline__ float f32x2_hsum(unsigned long long a, unsigned long long b) {
    unsigned long long s = add2(a, b);
    float2 f = *reinterpret_cast<float2*>(&s);
    return f.x + f.y;
}

// ---------------- init: poison history, seed h0 -------------------------------
__global__ void poison_kernel() {
    const float4 s = make_float4(SENT, SENT, SENT, SENT);
    float4* p = (float4*)g_hist;
    const int total = (SEQ + 1) * (DIMS / 4);
    for (int w = blockIdx.x * blockDim.x + threadIdx.x; w < total;
         w += gridDim.x * blockDim.x)
        p[w] = s;
}
__global__ void seed_kernel(const float* __restrict__ h0) {
    int i = blockIdx.x * blockDim.x + threadIdx.x;
    if (i < DIMS) g_hist[i] = h0[i];
}

// ---------------- phase 1: A = X @ W^T + b  (packed f32x2, double-buffered) ---
#define BM 128
#define BN 128
#define BK 16
#define KTILES (DIMS / BK)   // 128

__global__ __launch_bounds__(256) void gemm_kernel(
    const float* __restrict__ X, const float* __restrict__ W,
    const float* __restrict__ b, float* __restrict__ A)
{
    __shared__ __align__(16) float Xs[2][BK][BM];   // 16 KB
    __shared__ __align__(16) float Ws[2][BK][BN];   // 16 KB

    const int tid = threadIdx.x;
    const int m0  = blockIdx.y * BM;
    const int n0  = blockIdx.x * BN;
    const int tx  = tid & 15;       // column pair base: tx*2 + 32*jp
    const int ty  = tid >> 4;       // row: ty + 16*i
    const int lr  = tid >> 1;       // 0..127: tile row loaded by this thread
    const int lk  = (tid & 1) * 4;  // 0 or 4; this thread loads k: lk..lk+3, lk+8..lk+11

    const float* Xp = X + (size_t)(m0 + lr) * DIMS + lk;
    const float* Wp = W + (size_t)(n0 + lr) * DIMS + lk;

    unsigned long long acc[8][4];
#pragma unroll
    for (int i = 0; i < 8; i++)
#pragma unroll
        for (int jp = 0; jp < 4; jp++) acc[i][jp] = 0ull;

    // prologue: tile 0 -> buffer 0
    float4 xa = *(const float4*)(Xp + 0), xb = *(const float4*)(Xp + 8);
    float4 wa = *(const float4*)(Wp + 0), wb = *(const float4*)(Wp + 8);
    Xs[0][lk + 0][lr] = xa.x; Xs[0][lk + 1][lr] = xa.y;
    Xs[0][lk + 2][lr] = xa.z; Xs[0][lk + 3][lr] = xa.w;
    Xs[0][lk + 8][lr] = xb.x; Xs[0][lk + 9][lr] = xb.y;
    Xs[0][lk +10][lr] = xb.z; Xs[0][lk +11][lr] = xb.w;
    Ws[0][lk + 0][lr] = wa.x; Ws[0][lk + 1][lr] = wa.y;
    Ws[0][lk + 2][lr] = wa.z; Ws[0][lk + 3][lr] = wa.w;
    Ws[0][lk + 8][lr] = wb.x; Ws[0][lk + 9][lr] = wb.y;
    Ws[0][lk +10][lr] = wb.z; Ws[0][lk +11][lr] = wb.w;
    __syncthreads();

    for (int it = 0; it < KTILES; it++) {
        const int cur = it & 1, nxt = cur ^ 1;

        // prefetch next tile from global (overlaps with compute below)
        if (it + 1 < KTILES) {
            const int k0 = (it + 1) * BK;
            xa = *(const float4*)(Xp + k0);  xb = *(const float4*)(Xp + k0 + 8);
            wa = *(const float4*)(Wp + k0);  wb = *(const float4*)(Wp + k0 + 8);
        }

        // compute on current buffer
#pragma unroll
        for (int k = 0; k < BK; k++) {
            unsigned long long xd[8], wp[4];
#pragma unroll
            for (int i = 0; i < 8; i++) xd[i] = pack2(Xs[cur][k][ty + 16 * i]);
#pragma unroll
            for (int jp = 0; jp < 4; jp++)
                wp[jp] = *(const unsigned long long*)&Ws[cur][k][tx * 2 + 32 * jp];
#pragma unroll
            for (int i = 0; i < 8; i++)
#pragma unroll
                for (int jp = 0; jp < 4; jp++) ffma2(acc[i][jp], xd[i], wp[jp]);
        }

        // stage prefetched tile into the other buffer (no conflict with cur)
        if (it + 1 < KTILES) {
            Xs[nxt][lk + 0][lr] = xa.x; Xs[nxt][lk + 1][lr] = xa.y;
            Xs[nxt][lk + 2][lr] = xa.z; Xs[nxt][lk + 3][lr] = xa.w;
            Xs[nxt][lk + 8][lr] = xb.x; Xs[nxt][lk + 9][lr] = xb.y;
            Xs[nxt][lk +10][lr] = xb.z; Xs[nxt][lk +11][lr] = xb.w;
            Ws[nxt][lk + 0][lr] = wa.x; Ws[nxt][lk + 1][lr] = wa.y;
            Ws[nxt][lk + 2][lr] = wa.z; Ws[nxt][lk + 3][lr] = wa.w;
            Ws[nxt][lk + 8][lr] = wb.x; Ws[nxt][lk + 9][lr] = wb.y;
            Ws[nxt][lk +10][lr] = wb.z; Ws[nxt][lk +11][lr] = wb.w;
            __syncthreads();   // one bar per k-tile
        }
    }

    unsigned long long bp[4];
#pragma unroll
    for (int jp = 0; jp < 4; jp++)
        bp[jp] = *(const unsigned long long*)&b[n0 + tx * 2 + 32 * jp];
#pragma unroll
    for (int i = 0; i < 8; i++) {
        const int m = m0 + ty + 16 * i;
#pragma unroll
        for (int jp = 0; jp < 4; jp++) {
            *(unsigned long long*)&A[(size_t)m * DIMS + n0 + tx * 2 + 32 * jp] =
                add2(acc[i][jp], bp[jp]);
        }
    }
}

// ---------------- phase 2: persistent sequential RNN --------------------------
// EXACT R5 champion structure (7244us): 128 CTAs x 256 threads (8 warps, 2 rows
// each), value-signaled write-once history with sentinel poison, hot-spin
// payload polling, TWO bars per step, smem collect + tid<4 full-sector v4
// publish. Both bars and the single-sector publish are load-bearing (R7/R8).
#define NCTA 128
#define RPC  16
#define RNN_THREADS 256

__global__ __launch_bounds__(RNN_THREADS, 1) void rnn_kernel(
    const float* __restrict__ X, const float* __restrict__ Whh,
    float* __restrict__ out)
{
    __shared__ __align__(16) float4 h_s[DIMS / 4];  // 8 KB
    __shared__ __align__(16) float  c_s[RPC];       // this CTA's 16 new h

    const int tid  = threadIdx.x;
    const int wid  = tid >> 5;
    const int lane = tid & 31;
    const int cta  = blockIdx.x;
    const int row0 = cta * RPC + wid * 2;
    const int row1 = row0 + 1;

    // W_hh slice in registers as packed f32x2 pairs (2 rows per warp).
    ulonglong2 w0[16], w1[16];
    {
        const ulonglong2* W0 = (const ulonglong2*)(Whh + (size_t)row0 * DIMS);
        const ulonglong2* W1 = (const ulonglong2*)(Whh + (size_t)row1 * DIMS);
#pragma unroll
        for (int k = 0; k < 16; k++) {
            w0[k] = W0[lane + 32 * k];
            w1[k] = W1[lane + 32 * k];
        }
    }

    for (int t = 0; t < SEQ; t++) {
        const float4* hb = (const float4*)(g_hist + (size_t)t * DIMS);
        float4*       hn = (float4*)(g_hist + (size_t)(t + 1) * DIMS);

        // Step-constant operands, off the h critical chain.
        float a0 = 0.f, a1 = 0.f, xr0 = 0.f, xr1 = 0.f;
        if (lane == 0) {
            a0  = g_A[(size_t)t * DIMS + row0];
            a1  = g_A[(size_t)t * DIMS + row1];
            xr0 = X[(size_t)t * DIMS + row0];
            xr1 = X[(size_t)t * DIMS + row1];
        }

        // Ingest h_prev: each thread owns 2 of the 512 16B words; the payload
        // IS the signal (sentinel 2.0 can never be a tanh output / h0 value).
        {
            float4 va = ldg_vol_v4(hb + tid);
            float4 vb = ldg_vol_v4(hb + tid + RNN_THREADS);
            while (va.x == SENT || va.y == SENT || va.z == SENT || va.w == SENT)
                va = ldg_vol_v4(hb + tid);
            while (vb.x == SENT || vb.y == SENT || vb.z == SENT || vb.w == SENT)
                vb = ldg_vol_v4(hb + tid + RNN_THREADS);
            h_s[tid]               = va;
            h_s[tid + RNN_THREADS] = vb;
        }
        __syncthreads();   // h_s fully staged

        // 2 dot products per warp; W in registers, h broadcast from smem,
        // packed f32x2 FMA (2 MACs / instruction).
        unsigned long long a0x = 0ull, a0y = 0ull, a1x = 0ull, a1y = 0ull;
#pragma unroll
        for (int k = 0; k < 16; k++) {
            ulonglong2 hv = *(const ulonglong2*)&h_s[lane + 32 * k];
            ffma2(a0x, w0[k].x, hv.x);  ffma2(a0y, w0[k].y, hv.y);
            ffma2(a1x, w1[k].x, hv.x);  ffma2(a1y, w1[k].y, hv.y);
        }
        float acc0 = f32x2_hsum(a0x, a0y);
        float acc1 = f32x2_hsum(a1x, a1y);
#pragma unroll
        for (int o = 16; o > 0; o >>= 1) {
            acc0 += __shfl_xor_sync(0xffffffffu, acc0, o);
            acc1 += __shfl_xor_sync(0xffffffffu, acc1, o);
        }

        if (lane == 0) {
            float h0n = tanh_fast(a0 + acc0);
            float h1n = tanh_fast(a1 + acc1);
            c_s[wid * 2 + 0] = h0n;
            c_s[wid * 2 + 1] = h1n;
            out[(size_t)t * DIMS + row0] = xr0 + h0n;   // residual, off-chain
            out[(size_t)t * DIMS + row1] = xr1 + h1n;
        }
        __syncthreads();   // c_s complete; all h_s reads done before reuse

        // Publish this CTA's 4 words (write-once, full 16B sectors, single
        // publisher per sector; readers re-poll until all 4 lanes valid).
        if (tid < 4) stg_vol_v4(hn + cta * 4 + tid, *(const float4*)&c_s[tid * 4]);
    }
}

// ---------------- launch -------------------------------------------------------
extern "C" void kernel_launch(void* const* d_in, const int* in_sizes, int n_in,
                              void* d_out, int out_size) {
    const float* X    = (const float*)d_in[0];  // [SEQ, DIMS]
    const float* W_hi = (const float*)d_in[1];  // [DIMS, DIMS]
    const float* W_hh = (const float*)d_in[2];  // [DIMS, DIMS]
    const float* b    = (const float*)d_in[3];  // [DIMS]
    const float* h0   = (const float*)d_in[4];  // [DIMS]
    float* out = (float*)d_out;

    float* A;
    cudaGetSymbolAddress((void**)&A, g_A);

    poison_kernel<<<1024, 256>>>();
    seed_kernel<<<(DIMS + 255) / 256, 256>>>(h0);

    dim3 ggrid(DIMS / BN, SEQ / BM);            // (16, 32)
    gemm_kernel<<<ggrid, 256>>>(X, W_hi, b, A);

    rnn_kernel<<<NCTA, RNN_THREADS>>>(X, W_hh, out);
}